// round 15
// baseline (speedup 1.0000x reference)
#include <cuda_runtime.h>
#include <cuda_fp16.h>

#define N_NODES 100000
#define N_EDGES 3200000
#define IN_FEAT 512
#define HID 32
#define SCAN_BLK 512
#define SCAN_NBLK ((N_NODES + SCAN_BLK - 1) / SCAN_BLK)   // 196

// ---------------- device scratch (static, no allocation) ----------------
__device__ int    g_degi[N_NODES];
__device__ float  g_dinv[N_NODES];
__device__ int    g_rowstart[N_NODES + 1];
__device__ int    g_cursor[N_NODES];
__device__ int    g_blocksum[SCAN_NBLK];
__device__ int    g_blockoff[SCAN_NBLK];
__device__ int    g_csrc[N_EDGES];
// h stored as fp16: row = 32 halfs = 64 B
__device__ __half g_h[(size_t)N_NODES * HID];    // ping
__device__ __half g_agg[(size_t)N_NODES * HID];  // pong

// ---------------- f32x2 helpers ----------------
__device__ __forceinline__ unsigned long long fma2(unsigned long long a,
                                                   unsigned long long b,
                                                   unsigned long long c) {
    unsigned long long d;
    asm("fma.rn.f32x2 %0, %1, %2, %3;" : "=l"(d) : "l"(a), "l"(b), "l"(c));
    return d;
}
__device__ __forceinline__ void unpack2(unsigned long long v, float& lo, float& hi) {
    asm("mov.b64 {%0, %1}, %2;" : "=f"(lo), "=f"(hi) : "l"(v));
}

// ---------------- degree / CSR build ----------------
__global__ void zero_degi_kernel() {
    int i = blockIdx.x * blockDim.x + threadIdx.x;
    if (i < N_NODES) g_degi[i] = 0;
}

__global__ void degi_kernel(const int* __restrict__ dst) {
    int e = blockIdx.x * blockDim.x + threadIdx.x;
    if (e < N_EDGES) atomicAdd(&g_degi[dst[e]], 1);
}

// block-local exclusive scan of degrees; also computes dinv (fused).
__global__ void scan_block_kernel() {
    __shared__ int sh[SCAN_BLK];
    int i = blockIdx.x * SCAN_BLK + threadIdx.x;
    int v = (i < N_NODES) ? g_degi[i] : 0;
    if (i < N_NODES) g_dinv[i] = rsqrtf((float)v + 1.0f);
    sh[threadIdx.x] = v;
    __syncthreads();
    #pragma unroll
    for (int off = 1; off < SCAN_BLK; off <<= 1) {
        int t = (threadIdx.x >= off) ? sh[threadIdx.x - off] : 0;
        __syncthreads();
        sh[threadIdx.x] += t;
        __syncthreads();
    }
    if (i < N_NODES) g_rowstart[i] = sh[threadIdx.x] - v;
    if (threadIdx.x == SCAN_BLK - 1) g_blocksum[blockIdx.x] = sh[SCAN_BLK - 1];
}

// parallel scan of the 196 block sums (single 256-thread block).
__global__ void scan_tops_kernel() {
    __shared__ int sh[256];
    int t = threadIdx.x;
    int v = (t < SCAN_NBLK) ? g_blocksum[t] : 0;
    sh[t] = v;
    __syncthreads();
    #pragma unroll
    for (int off = 1; off < 256; off <<= 1) {
        int x = (t >= off) ? sh[t - off] : 0;
        __syncthreads();
        sh[t] += x;
        __syncthreads();
    }
    if (t < SCAN_NBLK) g_blockoff[t] = sh[t] - v;
    if (t == 255) g_rowstart[N_NODES] = sh[255];
}

__global__ void scan_add_kernel() {
    int i = blockIdx.x * blockDim.x + threadIdx.x;
    if (i < N_NODES) {
        int v = g_rowstart[i] + g_blockoff[i >> 9];
        g_rowstart[i] = v;
        g_cursor[i] = v;
    }
}

__global__ void fill_kernel(const int* __restrict__ src, const int* __restrict__ dst) {
    int e = blockIdx.x * blockDim.x + threadIdx.x;
    if (e < N_EDGES) {
        int d = dst[e];
        int pos = atomicAdd(&g_cursor[d], 1);
        g_csrc[pos] = src[e];
    }
}

// ---------------- GEMM1: [N,512] @ [512,32], f32x2, double-buffered --------
// (unchanged from R14: 139 us, crossbar-bound; TF32 mma rewrite is the
//  round-15 candidate if gathers stop being the bottleneck)
#define G1_ROWS 256
#define G1_TK 16
#define G1_NT (IN_FEAT / G1_TK)   // 32 tiles
__global__ __launch_bounds__(256, 3) void gemm1_kernel(
    const float* __restrict__ x, const float* __restrict__ W,
    __half* __restrict__ hh)
{
    __shared__ float2 Xp[2][G1_TK][G1_ROWS / 2];   // 32 KB
    __shared__ float2 Ws2[2][G1_TK][HID];          // 8 KB

    int tid  = threadIdx.x;
    int w    = tid >> 5;
    int lane = tid & 31;
    int cid  = w & 3;
    int pgrp = w >> 2;
    int rowbase = blockIdx.x * G1_ROWS;

    float4 xv4[4];
    float  wv[2];

    unsigned long long acc[2][8];
    #pragma unroll
    for (int g = 0; g < 2; g++)
        #pragma unroll
        for (int c = 0; c < 8; c++) acc[g][c] = 0ull;

    auto ldg_tile = [&](int t) {
        int k0 = t * G1_TK;
        #pragma unroll
        for (int i = 0; i < 4; i++) {
            int flat = tid + i * 256;            // 0..1023
            int r  = flat >> 2;
            int c4 = flat & 3;
            int gr = rowbase + r;
            if (gr >= N_NODES) gr = N_NODES - 1;
            xv4[i] = *(const float4*)(x + (size_t)gr * IN_FEAT + k0 + c4 * 4);
        }
        #pragma unroll
        for (int i = 0; i < 2; i++) {
            int idx = tid + i * 256;             // 0..511
            int kk = idx >> 5;
            int c  = idx & 31;
            wv[i] = W[(size_t)(k0 + kk) * HID + c];
        }
    };
    auto sts_tile = [&](int nb) {
        #pragma unroll
        for (int i = 0; i < 4; i++) {
            int flat = tid + i * 256;
            int r  = flat >> 2;
            int c4 = flat & 3;
            int pr = r >> 1, comp = r & 1;
            (&Xp[nb][c4 * 4 + 0][pr].x)[comp] = xv4[i].x;
            (&Xp[nb][c4 * 4 + 1][pr].x)[comp] = xv4[i].y;
            (&Xp[nb][c4 * 4 + 2][pr].x)[comp] = xv4[i].z;
            (&Xp[nb][c4 * 4 + 3][pr].x)[comp] = xv4[i].w;
        }
        #pragma unroll
        for (int i = 0; i < 2; i++) {
            int idx = tid + i * 256;
            int kk = idx >> 5;
            int c  = idx & 31;
            Ws2[nb][kk][c] = make_float2(wv[i], wv[i]);
        }
    };

    ldg_tile(0);
    sts_tile(0);
    __syncthreads();

    for (int t = 0; t < G1_NT; t++) {
        int buf = t & 1;
        if (t + 1 < G1_NT) ldg_tile(t + 1);

        #pragma unroll
        for (int kk = 0; kk < G1_TK; kk++) {
            ulonglong2 xp = *(const ulonglong2*)(&Xp[buf][kk][pgrp * 64 + 2 * lane]);
            #pragma unroll
            for (int c2 = 0; c2 < 4; c2++) {
                ulonglong2 wp = *(const ulonglong2*)(&Ws2[buf][kk][cid * 8 + 2 * c2]);
                acc[0][2*c2+0] = fma2(xp.x, wp.x, acc[0][2*c2+0]);
                acc[0][2*c2+1] = fma2(xp.x, wp.y, acc[0][2*c2+1]);
                acc[1][2*c2+0] = fma2(xp.y, wp.x, acc[1][2*c2+0]);
                acc[1][2*c2+1] = fma2(xp.y, wp.y, acc[1][2*c2+1]);
            }
        }

        if (t + 1 < G1_NT) sts_tile((t + 1) & 1);
        __syncthreads();
    }

    // epilogue: unpack, scale by dinv, convert fp16, store uint4 (8 cols)
    #pragma unroll
    for (int g = 0; g < 2; g++) {
        int P  = pgrp * 64 + 2 * lane + g;
        int r0 = 2 * P + rowbase;
        float lo[8], hi[8];
        #pragma unroll
        for (int c = 0; c < 8; c++) unpack2(acc[g][c], lo[c], hi[c]);
        if (r0 < N_NODES) {
            float d0 = g_dinv[r0];
            __half2 h[4];
            #pragma unroll
            for (int q = 0; q < 4; q++)
                h[q] = __floats2half2_rn(lo[2*q] * d0, lo[2*q+1] * d0);
            *(uint4*)(&hh[(size_t)r0 * HID + cid * 8]) = *(const uint4*)h;
        }
        int r1 = r0 + 1;
        if (r1 < N_NODES) {
            float d1 = g_dinv[r1];
            __half2 h[4];
            #pragma unroll
            for (int q = 0; q < 4; q++)
                h[q] = __floats2half2_rn(hi[2*q] * d1, hi[2*q+1] * d1);
            *(uint4*)(&hh[(size_t)r1 * HID + cid * 8]) = *(const uint4*)h;
        }
    }
}

// ---------------- batched gather core (MLP-maximized) ----------------
// Per 32-edge block: 1 csrc LDG; two 16-edge batches where all 16 shfls and
// all 16 predicated LDGs are issued before any consumption (MLP=16); the
// predicate (j < jn) is warp-uniform, so the remainder uses the SAME path.
// 4 independent accumulator chains.
__device__ __forceinline__ float gather_sum(const __half* __restrict__ hh_in,
                                            int start, int end, int lane)
{
    const __half hzero = __float2half(0.0f);
    float acc0 = 0.f, acc1 = 0.f, acc2 = 0.f, acc3 = 0.f;
    for (int base = start; base < end; base += 32) {
        int nn = end - base;                       // >0, may exceed 32
        int sidx = (base + lane < end) ? g_csrc[base + lane] : 0;
        #pragma unroll
        for (int h16 = 0; h16 < 2; h16++) {
            int jn = nn - h16 * 16;                // remaining in this batch
            __half vals[16];
            #pragma unroll
            for (int j = 0; j < 16; j++) {
                int s = __shfl_sync(0xffffffffu, sidx, h16 * 16 + j);
                vals[j] = (j < jn) ? hh_in[(size_t)s * HID + lane] : hzero;
            }
            #pragma unroll
            for (int j = 0; j < 16; j += 4) {
                acc0 += __half2float(vals[j + 0]);
                acc1 += __half2float(vals[j + 1]);
                acc2 += __half2float(vals[j + 2]);
                acc3 += __half2float(vals[j + 3]);
            }
        }
    }
    return (acc0 + acc1) + (acc2 + acc3);
}

// ---------------- fused gather + next-layer GEMM (fp16 h) ----------------
__global__ __launch_bounds__(256) void gather_gemm_kernel(
    const __half* __restrict__ hh_in, const float* __restrict__ b,
    const float* __restrict__ W, __half* __restrict__ hh_out)
{
    __shared__ float Ws[HID * HID];   // Ws[k*32 + col] = W[k][col]
    for (int i = threadIdx.x; i < HID * HID; i += 256) Ws[i] = W[i];
    __syncthreads();

    int node = blockIdx.x * 8 + (threadIdx.x >> 5);
    int lane = threadIdx.x & 31;
    int start = g_rowstart[node];
    int end   = g_rowstart[node + 1];

    float dv   = g_dinv[node];
    float self = __half2float(hh_in[(size_t)node * HID + lane]);
    float bb   = b[lane];

    float sum = gather_sum(hh_in, start, end, lane);
    float v = fmaxf(dv * (sum + self) + bb, 0.0f);

    float o = 0.f;
    #pragma unroll
    for (int k = 0; k < HID; k++) {
        float xv = __shfl_sync(0xffffffffu, v, k);
        o += xv * Ws[k * HID + lane];
    }
    hh_out[(size_t)node * HID + lane] = __float2half(o * dv);
}

// ---------------- fused layer-3 gather + MLP head (fp16 h) ----------------
__global__ __launch_bounds__(256) void gather_mlp_kernel(
    const __half* __restrict__ hh, const float* __restrict__ b3,
    const float* __restrict__ l1W, const float* __restrict__ l1b,
    const float* __restrict__ l2W, const float* __restrict__ l2b,
    float* __restrict__ out)
{
    int node = blockIdx.x * 8 + (threadIdx.x >> 5);
    int lane = threadIdx.x & 31;
    int start = g_rowstart[node];
    int end   = g_rowstart[node + 1];

    float dv   = g_dinv[node];
    float self = __half2float(hh[(size_t)node * HID + lane]);
    float bb   = b3[lane];

    float sum = gather_sum(hh, start, end, lane);
    float v = fmaxf(dv * (sum + self) + bb, 0.0f);  // x3

    // lin1: [32] -> [16], relu
    float a1 = 0.f;
    #pragma unroll
    for (int k = 0; k < 32; k++) {
        float xv = __shfl_sync(0xffffffffu, v, k);
        if (lane < 16) a1 += xv * l1W[k * 16 + lane];
    }
    float h1 = (lane < 16) ? fmaxf(a1 + l1b[lane], 0.0f) : 0.0f;

    // lin2: [16] -> [10]
    float a2 = 0.f;
    #pragma unroll
    for (int j = 0; j < 16; j++) {
        float hv = __shfl_sync(0xffffffffu, h1, j);
        if (lane < 10) a2 += hv * l2W[j * 10 + lane];
    }
    if (lane < 10) out[(size_t)node * 10 + lane] = a2 + l2b[lane];
}

// ---------------- host ----------------
extern "C" void kernel_launch(void* const* d_in, const int* in_sizes, int n_in,
                              void* d_out, int out_size)
{
    const float* x0  = (const float*)d_in[0];
    const int*   ei  = (const int*)d_in[1];   // edge_index int32
    // d_in[2] = batch (unused)
    const float* W1  = (const float*)d_in[3];
    const float* b1  = (const float*)d_in[4];
    const float* W2  = (const float*)d_in[5];
    const float* b2  = (const float*)d_in[6];
    const float* W3  = (const float*)d_in[7];
    const float* b3  = (const float*)d_in[8];
    const float* l1W = (const float*)d_in[9];
    const float* l1b = (const float*)d_in[10];
    const float* l2W = (const float*)d_in[11];
    const float* l2b = (const float*)d_in[12];
    float* out = (float*)d_out;

    const int* src = ei;
    const int* dst = ei + N_EDGES;

    __half *hbuf = nullptr, *abuf = nullptr;
    cudaGetSymbolAddress((void**)&hbuf, g_h);
    cudaGetSymbolAddress((void**)&abuf, g_agg);

    static cudaStream_t s_side = nullptr;
    static cudaEvent_t  s_fork = nullptr, s_join = nullptr;
    if (s_side == nullptr) {
        cudaStreamCreateWithFlags(&s_side, cudaStreamNonBlocking);
        cudaEventCreateWithFlags(&s_fork, cudaEventDisableTiming);
        cudaEventCreateWithFlags(&s_join, cudaEventDisableTiming);
    }

    const int nodeBlocks = (N_NODES + 255) / 256;   // 391
    const int edgeBlocks = N_EDGES / 256;           // 12500
    const int warpBlocks = N_NODES / 8;             // 12500
    const int g1Blocks   = (N_NODES + G1_ROWS - 1) / G1_ROWS;  // 391

    // ---- CSR build prefix (degrees + dinv) ----
    zero_degi_kernel<<<nodeBlocks, 256>>>();
    degi_kernel<<<edgeBlocks, 256>>>(dst);
    scan_block_kernel<<<SCAN_NBLK, SCAN_BLK>>>();

    // ---- fork: gemm1 needs only dinv; CSR tail is independent ----
    cudaEventRecord(s_fork, 0);
    cudaStreamWaitEvent(s_side, s_fork, 0);
    gemm1_kernel<<<g1Blocks, 256, 0, s_side>>>(x0, W1, hbuf);       // hh1

    scan_tops_kernel<<<1, 256>>>();
    scan_add_kernel<<<nodeBlocks, 256>>>();
    fill_kernel<<<edgeBlocks, 256>>>(src, dst);

    // ---- join ----
    cudaEventRecord(s_join, s_side);
    cudaStreamWaitEvent(0, s_join, 0);

    // ---- gather1 + gemm2 fused ----
    gather_gemm_kernel<<<warpBlocks, 256>>>(hbuf, b1, W2, abuf);    // hh2

    // ---- gather2 + gemm3 fused ----
    gather_gemm_kernel<<<warpBlocks, 256>>>(abuf, b2, W3, hbuf);    // hh3

    // ---- gather3 + MLP head fused ----
    gather_mlp_kernel<<<warpBlocks, 256>>>(hbuf, b3, l1W, l1b, l2W, l2b, out);
}

// round 16
// speedup vs baseline: 1.4463x; 1.4463x over previous
#include <cuda_runtime.h>
#include <cuda_fp16.h>
#include <cstdint>

#define N_NODES 100000
#define N_EDGES 3200000
#define IN_FEAT 512
#define HID 32
#define SCAN_BLK 512
#define SCAN_NBLK ((N_NODES + SCAN_BLK - 1) / SCAN_BLK)   // 196

// ---------------- device scratch (static, no allocation) ----------------
__device__ int    g_degi[N_NODES];
__device__ float  g_dinv[N_NODES];
__device__ int    g_rowstart[N_NODES + 1];
__device__ int    g_cursor[N_NODES];
__device__ int    g_blocksum[SCAN_NBLK];
__device__ int    g_blockoff[SCAN_NBLK];
__device__ int    g_csrc[N_EDGES];
// h stored as fp16: row = 32 halfs = 64 B
__device__ __half g_h[(size_t)N_NODES * HID];    // ping
__device__ __half g_agg[(size_t)N_NODES * HID];  // pong

// ---------------- degree / CSR build ----------------
__global__ void zero_degi_kernel() {
    int i = blockIdx.x * blockDim.x + threadIdx.x;
    if (i < N_NODES) g_degi[i] = 0;
}

__global__ void degi_kernel(const int* __restrict__ dst) {
    int e = blockIdx.x * blockDim.x + threadIdx.x;
    if (e < N_EDGES) atomicAdd(&g_degi[dst[e]], 1);
}

// block-local exclusive scan of degrees; also computes dinv (fused).
__global__ void scan_block_kernel() {
    __shared__ int sh[SCAN_BLK];
    int i = blockIdx.x * SCAN_BLK + threadIdx.x;
    int v = (i < N_NODES) ? g_degi[i] : 0;
    if (i < N_NODES) g_dinv[i] = rsqrtf((float)v + 1.0f);
    sh[threadIdx.x] = v;
    __syncthreads();
    #pragma unroll
    for (int off = 1; off < SCAN_BLK; off <<= 1) {
        int t = (threadIdx.x >= off) ? sh[threadIdx.x - off] : 0;
        __syncthreads();
        sh[threadIdx.x] += t;
        __syncthreads();
    }
    if (i < N_NODES) g_rowstart[i] = sh[threadIdx.x] - v;
    if (threadIdx.x == SCAN_BLK - 1) g_blocksum[blockIdx.x] = sh[SCAN_BLK - 1];
}

// parallel scan of the 196 block sums (single 256-thread block).
__global__ void scan_tops_kernel() {
    __shared__ int sh[256];
    int t = threadIdx.x;
    int v = (t < SCAN_NBLK) ? g_blocksum[t] : 0;
    sh[t] = v;
    __syncthreads();
    #pragma unroll
    for (int off = 1; off < 256; off <<= 1) {
        int x = (t >= off) ? sh[t - off] : 0;
        __syncthreads();
        sh[t] += x;
        __syncthreads();
    }
    if (t < SCAN_NBLK) g_blockoff[t] = sh[t] - v;
    if (t == 255) g_rowstart[N_NODES] = sh[255];
}

__global__ void scan_add_kernel() {
    int i = blockIdx.x * blockDim.x + threadIdx.x;
    if (i < N_NODES) {
        int v = g_rowstart[i] + g_blockoff[i >> 9];
        g_rowstart[i] = v;
        g_cursor[i] = v;
    }
}

__global__ void fill_kernel(const int* __restrict__ src, const int* __restrict__ dst) {
    int e = blockIdx.x * blockDim.x + threadIdx.x;
    if (e < N_EDGES) {
        int d = dst[e];
        int pos = atomicAdd(&g_cursor[d], 1);
        g_csrc[pos] = src[e];
    }
}

// ---------------- GEMM1: TF32 tensor-core mma, double-buffered -------------
// [N,512] @ [512,32]. 256 threads, tile 128 rows x 32 cols, K-chunk 32.
// Warp w owns rows w*16..w*16+15, all 32 cols (4 n-tiles of m16n8k8).
// Smem pitch 36 words: frag-load bank = 4*(lane>>2) + (lane&3) -> conflict-free.
// TF32 conversion (cvt.rna) applied once at STS time. Accums fp32 in regs.
// Epilogue: scale by dinv[row], store fp16 half2 (D-frag cols are adjacent).
#define G1_ROWS 128
#define G1_TK 32
#define G1_NT (IN_FEAT / G1_TK)   // 16 chunks
#define G1_PITCH 36

__device__ __forceinline__ uint32_t f2tf32(float f) {
    uint32_t r;
    asm("cvt.rna.tf32.f32 %0, %1;" : "=r"(r) : "f"(f));
    return r;
}

__device__ __forceinline__ void mma_tf32(float* d,
    uint32_t a0, uint32_t a1, uint32_t a2, uint32_t a3,
    uint32_t b0, uint32_t b1)
{
    asm volatile(
        "mma.sync.aligned.m16n8k8.row.col.f32.tf32.tf32.f32 "
        "{%0,%1,%2,%3}, {%4,%5,%6,%7}, {%8,%9}, {%0,%1,%2,%3};"
        : "+f"(d[0]), "+f"(d[1]), "+f"(d[2]), "+f"(d[3])
        : "r"(a0), "r"(a1), "r"(a2), "r"(a3), "r"(b0), "r"(b1));
}

__global__ __launch_bounds__(256, 4) void gemm1_kernel(
    const float* __restrict__ x, const float* __restrict__ W,
    __half* __restrict__ hh)
{
    __shared__ uint32_t Xs[2][G1_ROWS][G1_PITCH];   // 36 KB (tf32 bits)
    __shared__ uint32_t WsT[2][HID][G1_PITCH];      // 9 KB, [col][k]

    int tid  = threadIdx.x;
    int warp = tid >> 5;
    int lane = tid & 31;
    int gid  = lane >> 2;        // group id (row within frag)
    int tig  = lane & 3;         // thread in group (k / col selector)
    int rowbase = blockIdx.x * G1_ROWS;

    float4 xv[4];   // X staging: 128x32 = 1024 f4 / 256 thr = 4
    float4 wv;      // W staging: 32x32 = 256 f4 / 256 thr = 1

    float acc[4][4];   // 4 n-tiles x 4 D-frag regs
    #pragma unroll
    for (int n = 0; n < 4; n++)
        #pragma unroll
        for (int q = 0; q < 4; q++) acc[n][q] = 0.f;

    auto ldg_tile = [&](int t) {
        int k0 = t * G1_TK;
        #pragma unroll
        for (int i = 0; i < 4; i++) {
            int flat = tid + i * 256;          // 0..1023
            int r  = flat >> 3;                // 0..127
            int c4 = flat & 7;                 // 0..7 (k/4)
            int gr = rowbase + r;
            if (gr >= N_NODES) gr = N_NODES - 1;
            xv[i] = *(const float4*)(x + (size_t)gr * IN_FEAT + k0 + c4 * 4);
        }
        int wk = tid >> 3;                     // 0..31 (k row)
        int wc = tid & 7;                      // col group
        wv = *(const float4*)(W + (size_t)(k0 + wk) * HID + wc * 4);
    };
    auto sts_tile = [&](int nb) {
        #pragma unroll
        for (int i = 0; i < 4; i++) {
            int flat = tid + i * 256;
            int r  = flat >> 3;
            int c4 = flat & 7;
            uint32_t p[4] = { f2tf32(xv[i].x), f2tf32(xv[i].y),
                              f2tf32(xv[i].z), f2tf32(xv[i].w) };
            *(uint4*)(&Xs[nb][r][c4 * 4]) = *(const uint4*)p;   // row pitch 144B, 16B-aligned
        }
        int wk = tid >> 3;
        int wc = tid & 7;
        WsT[nb][wc * 4 + 0][wk] = f2tf32(wv.x);
        WsT[nb][wc * 4 + 1][wk] = f2tf32(wv.y);
        WsT[nb][wc * 4 + 2][wk] = f2tf32(wv.z);
        WsT[nb][wc * 4 + 3][wk] = f2tf32(wv.w);
    };

    ldg_tile(0);
    sts_tile(0);
    __syncthreads();

    for (int t = 0; t < G1_NT; t++) {
        int buf = t & 1;
        if (t + 1 < G1_NT) ldg_tile(t + 1);

        #pragma unroll
        for (int s = 0; s < 4; s++) {          // 4 k-steps of 8
            int r0 = warp * 16 + gid;
            uint32_t a0 = Xs[buf][r0    ][s * 8 + tig    ];
            uint32_t a1 = Xs[buf][r0 + 8][s * 8 + tig    ];
            uint32_t a2 = Xs[buf][r0    ][s * 8 + tig + 4];
            uint32_t a3 = Xs[buf][r0 + 8][s * 8 + tig + 4];
            #pragma unroll
            for (int n = 0; n < 4; n++) {
                uint32_t b0 = WsT[buf][n * 8 + gid][s * 8 + tig    ];
                uint32_t b1 = WsT[buf][n * 8 + gid][s * 8 + tig + 4];
                mma_tf32(acc[n], a0, a1, a2, a3, b0, b1);
            }
        }

        if (t + 1 < G1_NT) sts_tile((t + 1) & 1);
        __syncthreads();
    }

    // epilogue: D-frag (c0,c1)=row gid cols 2tig,2tig+1; (c2,c3)=row gid+8.
    int row0 = rowbase + warp * 16 + gid;
    int row1 = row0 + 8;
    float d0 = g_dinv[(row0 < N_NODES) ? row0 : 0];
    float d1 = g_dinv[(row1 < N_NODES) ? row1 : 0];
    #pragma unroll
    for (int n = 0; n < 4; n++) {
        int col = n * 8 + tig * 2;
        if (row0 < N_NODES)
            *(__half2*)(&hh[(size_t)row0 * HID + col]) =
                __floats2half2_rn(acc[n][0] * d0, acc[n][1] * d0);
        if (row1 < N_NODES)
            *(__half2*)(&hh[(size_t)row1 * HID + col]) =
                __floats2half2_rn(acc[n][2] * d1, acc[n][3] * d1);
    }
}

// ---------------- fused gather + next-layer GEMM (fp16 h, R14 shape) -------
// warp per node, lane = feature column; one 64B coalesced __half load per
// edge across the warp; unconditional unrolled 32-edge blocks, dual acc chains.
__global__ __launch_bounds__(256) void gather_gemm_kernel(
    const __half* __restrict__ hh_in, const float* __restrict__ b,
    const float* __restrict__ W, __half* __restrict__ hh_out)
{
    __shared__ float Ws[HID * HID];   // Ws[k*32 + col] = W[k][col]
    for (int i = threadIdx.x; i < HID * HID; i += 256) Ws[i] = W[i];
    __syncthreads();

    int node = blockIdx.x * 8 + (threadIdx.x >> 5);
    int lane = threadIdx.x & 31;
    int start = g_rowstart[node];
    int end   = g_rowstart[node + 1];

    float acc0 = 0.f, acc1 = 0.f;
    for (int base = start; base < end; base += 32) {
        int e = base + lane;
        int sidx = (e < end) ? g_csrc[e] : 0;
        int n = end - base;
        if (n >= 32) {
            #pragma unroll
            for (int j = 0; j < 32; j += 2) {
                int s0 = __shfl_sync(0xffffffffu, sidx, j);
                int s1 = __shfl_sync(0xffffffffu, sidx, j + 1);
                acc0 += __half2float(hh_in[(size_t)s0 * HID + lane]);
                acc1 += __half2float(hh_in[(size_t)s1 * HID + lane]);
            }
        } else {
            for (int j = 0; j < n; j++) {
                int s = __shfl_sync(0xffffffffu, sidx, j);
                acc0 += __half2float(hh_in[(size_t)s * HID + lane]);
            }
        }
    }
    float dv = g_dinv[node];
    float self = __half2float(hh_in[(size_t)node * HID + lane]);
    float v = fmaxf(dv * (acc0 + acc1 + self) + b[lane], 0.0f);

    float o = 0.f;
    #pragma unroll
    for (int k = 0; k < HID; k++) {
        float xv = __shfl_sync(0xffffffffu, v, k);
        o += xv * Ws[k * HID + lane];
    }
    hh_out[(size_t)node * HID + lane] = __float2half(o * dv);
}

// ---------------- fused layer-3 gather + MLP head (fp16 h) ----------------
__global__ __launch_bounds__(256) void gather_mlp_kernel(
    const __half* __restrict__ hh, const float* __restrict__ b3,
    const float* __restrict__ l1W, const float* __restrict__ l1b,
    const float* __restrict__ l2W, const float* __restrict__ l2b,
    float* __restrict__ out)
{
    int node = blockIdx.x * 8 + (threadIdx.x >> 5);
    int lane = threadIdx.x & 31;
    int start = g_rowstart[node];
    int end   = g_rowstart[node + 1];

    float acc0 = 0.f, acc1 = 0.f;
    for (int base = start; base < end; base += 32) {
        int e = base + lane;
        int sidx = (e < end) ? g_csrc[e] : 0;
        int n = end - base;
        if (n >= 32) {
            #pragma unroll
            for (int j = 0; j < 32; j += 2) {
                int s0 = __shfl_sync(0xffffffffu, sidx, j);
                int s1 = __shfl_sync(0xffffffffu, sidx, j + 1);
                acc0 += __half2float(hh[(size_t)s0 * HID + lane]);
                acc1 += __half2float(hh[(size_t)s1 * HID + lane]);
            }
        } else {
            for (int j = 0; j < n; j++) {
                int s = __shfl_sync(0xffffffffu, sidx, j);
                acc0 += __half2float(hh[(size_t)s * HID + lane]);
            }
        }
    }
    float dv = g_dinv[node];
    float self = __half2float(hh[(size_t)node * HID + lane]);
    float v = fmaxf(dv * (acc0 + acc1 + self) + b3[lane], 0.0f);  // x3

    // lin1: [32] -> [16], relu
    float a1 = 0.f;
    #pragma unroll
    for (int k = 0; k < 32; k++) {
        float xv = __shfl_sync(0xffffffffu, v, k);
        if (lane < 16) a1 += xv * l1W[k * 16 + lane];
    }
    float h1 = (lane < 16) ? fmaxf(a1 + l1b[lane], 0.0f) : 0.0f;

    // lin2: [16] -> [10]
    float a2 = 0.f;
    #pragma unroll
    for (int j = 0; j < 16; j++) {
        float hv = __shfl_sync(0xffffffffu, h1, j);
        if (lane < 10) a2 += hv * l2W[j * 10 + lane];
    }
    if (lane < 10) out[(size_t)node * 10 + lane] = a2 + l2b[lane];
}

// ---------------- host ----------------
extern "C" void kernel_launch(void* const* d_in, const int* in_sizes, int n_in,
                              void* d_out, int out_size)
{
    const float* x0  = (const float*)d_in[0];
    const int*   ei  = (const int*)d_in[1];   // edge_index int32
    // d_in[2] = batch (unused)
    const float* W1  = (const float*)d_in[3];
    const float* b1  = (const float*)d_in[4];
    const float* W2  = (const float*)d_in[5];
    const float* b2  = (const float*)d_in[6];
    const float* W3  = (const float*)d_in[7];
    const float* b3  = (const float*)d_in[8];
    const float* l1W = (const float*)d_in[9];
    const float* l1b = (const float*)d_in[10];
    const float* l2W = (const float*)d_in[11];
    const float* l2b = (const float*)d_in[12];
    float* out = (float*)d_out;

    const int* src = ei;
    const int* dst = ei + N_EDGES;

    __half *hbuf = nullptr, *abuf = nullptr;
    cudaGetSymbolAddress((void**)&hbuf, g_h);
    cudaGetSymbolAddress((void**)&abuf, g_agg);

    static cudaStream_t s_side = nullptr;
    static cudaEvent_t  s_fork = nullptr, s_join = nullptr;
    if (s_side == nullptr) {
        cudaStreamCreateWithFlags(&s_side, cudaStreamNonBlocking);
        cudaEventCreateWithFlags(&s_fork, cudaEventDisableTiming);
        cudaEventCreateWithFlags(&s_join, cudaEventDisableTiming);
    }

    const int nodeBlocks = (N_NODES + 255) / 256;   // 391
    const int edgeBlocks = N_EDGES / 256;           // 12500
    const int warpBlocks = N_NODES / 8;             // 12500
    const int g1Blocks   = (N_NODES + G1_ROWS - 1) / G1_ROWS;  // 782

    // ---- CSR build prefix (degrees + dinv) ----
    zero_degi_kernel<<<nodeBlocks, 256>>>();
    degi_kernel<<<edgeBlocks, 256>>>(dst);
    scan_block_kernel<<<SCAN_NBLK, SCAN_BLK>>>();

    // ---- fork: gemm1 needs only dinv; CSR tail is independent ----
    cudaEventRecord(s_fork, 0);
    cudaStreamWaitEvent(s_side, s_fork, 0);
    gemm1_kernel<<<g1Blocks, 256, 0, s_side>>>(x0, W1, hbuf);       // hh1

    scan_tops_kernel<<<1, 256>>>();
    scan_add_kernel<<<nodeBlocks, 256>>>();
    fill_kernel<<<edgeBlocks, 256>>>(src, dst);

    // ---- join ----
    cudaEventRecord(s_join, s_side);
    cudaStreamWaitEvent(0, s_join, 0);

    // ---- gather1 + gemm2 fused ----
    gather_gemm_kernel<<<warpBlocks, 256>>>(hbuf, b1, W2, abuf);    // hh2

    // ---- gather2 + gemm3 fused ----
    gather_gemm_kernel<<<warpBlocks, 256>>>(abuf, b2, W3, hbuf);    // hh3

    // ---- gather3 + MLP head fused ----
    gather_mlp_kernel<<<warpBlocks, 256>>>(hbuf, b3, l1W, l1b, l2W, l2b, out);
}